// round 16
// baseline (speedup 1.0000x reference)
#include <cuda_runtime.h>
#include <cuda_fp16.h>
#include <cstdint>

#define HID 256
#define MTILE 64

#define AROWB 528
// ---- smem byte offsets (16B aligned) ----
#define OFF_A    0        // 64 * 528 = 33792
#define OFF_B1   33792    // 128 half2
#define OFF_B2   34304    // 128 half2
#define OFF_B3   34816    // 4 f32
#define OFF_W0   34832    // 768 f32
#define OFF_CV   37904    // 256 f32
#define OFF_RGB  38928    // 192 f32
#define SMEM_TOT 39696

// B in PLANE-SPLIT mma-fragment order (coalesced LDG.128):
// uint32 index = (((((l*4 + wn)*16 + ks)*4 + rc)*32 + lane)*4 + q), r = rc*4+q
// value = half2( W[k][n], W[k+1][n] ), n = wn*64 + (r>>1)*8 + lane/4,
//         k = ks*16 + (r&1)*8 + (lane&3)*2
__device__ __align__(16) uint32_t g_bfrag[65536];
// W3 head fragments: [ks16][lane32] x 2 regs (cols 3..7 zero)
__device__ __align__(16) uint2 g_w3f[512];
__device__ float g_cstyle[16 * HID];

// ---------- helpers ----------
__device__ __forceinline__ uint32_t s2u(const void* p) {
    uint32_t a;
    asm("{ .reg .u64 t; cvta.to.shared.u64 t, %1; cvt.u32.u64 %0, t; }" : "=r"(a) : "l"(p));
    return a;
}
__device__ __forceinline__ void ldsm4(uint32_t* r, uint32_t addr) {
    asm volatile("ldmatrix.sync.aligned.m8n8.x4.shared.b16 {%0,%1,%2,%3}, [%4];"
                 : "=r"(r[0]), "=r"(r[1]), "=r"(r[2]), "=r"(r[3]) : "r"(addr));
}
__device__ __forceinline__ uint4 ldcg(const uint4* p) {
    uint4 v;
    asm("ld.global.cg.v4.u32 {%0,%1,%2,%3}, [%4];"
        : "=r"(v.x), "=r"(v.y), "=r"(v.z), "=r"(v.w) : "l"(p));
    return v;
}
__device__ __forceinline__ void mma16816h(uint32_t* d, const uint32_t* a, uint32_t b0, uint32_t b1) {
    asm volatile("mma.sync.aligned.m16n8k16.row.col.f16.f16.f16.f16 "
                 "{%0,%1}, {%2,%3,%4,%5}, {%6,%7}, {%0,%1};"
                 : "+r"(d[0]), "+r"(d[1])
                 : "r"(a[0]), "r"(a[1]), "r"(a[2]), "r"(a[3]), "r"(b0), "r"(b1));
}
__device__ __forceinline__ void mma16816f(float* d, const uint32_t* a, uint32_t b0, uint32_t b1) {
    asm volatile("mma.sync.aligned.m16n8k16.row.col.f32.f16.f16.f32 "
                 "{%0,%1,%2,%3}, {%4,%5,%6,%7}, {%8,%9}, {%0,%1,%2,%3};"
                 : "+f"(d[0]), "+f"(d[1]), "+f"(d[2]), "+f"(d[3])
                 : "r"(a[0]), "r"(a[1]), "r"(a[2]), "r"(a[3]), "r"(b0), "r"(b1));
}
__device__ __forceinline__ uint32_t pack_h2(float lo, float hi) {
    __half2 h = __floats2half2_rn(lo, hi);
    return *(uint32_t*)&h;
}
// tanh-form gelu on a packed half2
__device__ __forceinline__ uint32_t gelu_h2(uint32_t xu) {
    const __half2 C0 = __float2half2_rn(0.7978845608f);
    const __half2 C1 = __float2half2_rn(0.0356774081f);
    const __half2 H5 = __float2half2_rn(0.5f);
    __half2 x = *(__half2*)&xu;
    __half2 x2 = __hmul2(x, x);
    __half2 y = __hmul2(x, __hfma2(x2, C1, C0));
    uint32_t yu = *(uint32_t*)&y, tu;
    asm("tanh.approx.f16x2 %0, %1;" : "=r"(tu) : "r"(yu));
    __half2 t = *(__half2*)&tu;
    __half2 o = __hmul2(x, __hfma2(t, H5, H5));
    return *(uint32_t*)&o;
}

// ---------- merged pre-kernel ----------
__global__ void prep_all(const float* __restrict__ W1, const float* __restrict__ W2,
                         const int* __restrict__ sidx, const float* __restrict__ emb,
                         const float* __restrict__ W0, const float* __restrict__ b0,
                         const float* __restrict__ W3, int B) {
    if (blockIdx.x < 256) {
        int idx = blockIdx.x * 256 + threadIdx.x;    // uint32 index 0..65535
        int q    = idx & 3;
        int lane = (idx >> 2) & 31;
        int rc   = (idx >> 7) & 3;
        int ks   = (idx >> 9) & 15;
        int wn   = (idx >> 13) & 3;
        int l    = (idx >> 15) & 1;
        int r = rc * 4 + q;
        int n = wn * 64 + (r >> 1) * 8 + (lane >> 2);
        int k = ks * 16 + (r & 1) * 8 + (lane & 3) * 2;
        const float* Wm = l ? W2 : W1;
        g_bfrag[idx] = pack_h2(Wm[k * HID + n], Wm[(k + 1) * HID + n]);
    } else if ((int)blockIdx.x < 256 + B) {
        int b = blockIdx.x - 256, j = threadIdx.x;
        int s = sidx[b];
        float acc = b0[j];
#pragma unroll 8
        for (int k = 0; k < 64; k++)
            acc = fmaf(emb[s * 64 + k], W0[(3 + k) * HID + j], acc);
        g_cstyle[b * HID + j] = acc;
    } else {
        for (int e = threadIdx.x; e < 512; e += 256) {
            int ks = e >> 5, lane = e & 31;
            int n = lane >> 2;
            int k0 = ks * 16 + (lane & 3) * 2;
            float v00 = (n < 3) ? W3[k0 * 3 + n] : 0.f;
            float v01 = (n < 3) ? W3[(k0 + 1) * 3 + n] : 0.f;
            float v10 = (n < 3) ? W3[(k0 + 8) * 3 + n] : 0.f;
            float v11 = (n < 3) ? W3[(k0 + 9) * 3 + n] : 0.f;
            g_w3f[e] = make_uint2(pack_h2(v00, v01), pack_h2(v10, v11));
        }
    }
}

// ---------- main kernel ----------
// Software-pipelined layer: A one step ahead, B double-buffered.
// bp points at (layer, wn) base + lane; per ks, 4 coalesced plane loads at +rc*32.
__device__ __forceinline__ void run_layer(uint32_t abase, const uint4* bp, const uint4* bpn,
                                          uint32_t C[4][8][2], uint4 bb[2][4]) {
    uint32_t ahA[4], ahB[4];
    ldsm4(ahA, abase);                 // (ks=0, mt=0)
#pragma unroll
    for (int ks = 0; ks < 16; ks++) {
        uint4* nxt = bb[(ks + 1) & 1];
        const uint4* np = (ks < 15) ? bp + (ks + 1) * 128 : bpn;
        if (np) {
            nxt[0] = ldcg(np);      nxt[1] = ldcg(np + 32);
            nxt[2] = ldcg(np + 64); nxt[3] = ldcg(np + 96);
        }
        const uint32_t* bw = (const uint32_t*)bb[ks & 1];
#pragma unroll
        for (int mt = 0; mt < 4; mt++) {
            const int nmt = (mt + 1) & 3;
            const int nks = (mt == 3) ? ks + 1 : ks;
            if (nks < 16)
                ldsm4(ahB, abase + (uint32_t)nmt * (16 * AROWB) + (uint32_t)nks * 32);
#pragma unroll
            for (int nt = 0; nt < 8; nt++)
                mma16816h(C[mt][nt], ahA, bw[2 * nt], bw[2 * nt + 1]);
#pragma unroll
            for (int q = 0; q < 4; q++) { uint32_t t = ahA[q]; ahA[q] = ahB[q]; ahB[q] = t; }
        }
    }
}

// epilogue: C(half2) + bias -> gelu -> A ; zero C
__device__ __forceinline__ void epi_gelu(char* sm, uint32_t C[4][8][2],
                                         int offB, int ng, int lane) {
    const uint32_t* bh = (const uint32_t*)(sm + offB) + ng * 32 + (lane & 3);
    const int r0b = lane >> 2;
#pragma unroll
    for (int nt = 0; nt < 8; nt++) {
        uint32_t bju = bh[nt * 4];
        __half2 bj = *(__half2*)&bju;
        int j0 = ng * 64 + nt * 8 + (lane & 3) * 2;
#pragma unroll
        for (int mt = 0; mt < 4; mt++) {
            int r0 = r0b + mt * 16, r1 = r0 + 8;
            __half2 c0 = *(__half2*)&C[mt][nt][0];
            __half2 c1 = *(__half2*)&C[mt][nt][1];
            __half2 s0 = __hadd2(c0, bj);
            __half2 s1 = __hadd2(c1, bj);
            *(uint32_t*)(sm + OFF_A + r0 * AROWB + j0 * 2) = gelu_h2(*(uint32_t*)&s0);
            *(uint32_t*)(sm + OFF_A + r1 * AROWB + j0 * 2) = gelu_h2(*(uint32_t*)&s1);
            C[mt][nt][0] = 0u; C[mt][nt][1] = 0u;
        }
    }
}

__global__ void __launch_bounds__(128, 4) nilut_mma(
    const float* __restrict__ rgb, const float* __restrict__ W0,
    const float* __restrict__ b1, const float* __restrict__ b2,
    const float* __restrict__ b3,
    float* __restrict__ out, int HW)
{
    extern __shared__ __align__(1024) char sm[];
    const uint32_t sb = s2u(sm);
    const int tid = threadIdx.x, wid = tid >> 5, lane = tid & 31;

    const int ng = wid;                 // 4 warps, each m64 x n64
    const int arow = lane & 15, ak16off = ((lane >> 4) & 1) * 16;

    const uint4* bp1 = (const uint4*)g_bfrag + (size_t)ng * 2048 + lane;
    const uint4* bp2 = (const uint4*)g_bfrag + (size_t)(4 + ng) * 2048 + lane;

    uint4 bb[2][4];
    bb[0][0] = ldcg(bp1);      bb[0][1] = ldcg(bp1 + 32);
    bb[0][2] = ldcg(bp1 + 64); bb[0][3] = ldcg(bp1 + 96);

    const int pix0 = blockIdx.x * MTILE;
    const int b = pix0 / HW, hw0 = pix0 - b * HW;

    float* b3s = (float*)(sm + OFF_B3);
    float* w0s  = (float*)(sm + OFF_W0);
    float* cvec = (float*)(sm + OFF_CV);
    float* rgbs = (float*)(sm + OFF_RGB);

    ((uint32_t*)(sm + OFF_B1))[tid] = pack_h2(b1[2 * tid], b1[2 * tid + 1]);
    ((uint32_t*)(sm + OFF_B2))[tid] = pack_h2(b2[2 * tid], b2[2 * tid + 1]);
    if (tid < 4) b3s[tid] = (tid < 3) ? b3[tid] : 0.f;
    for (int i = tid; i < 768; i += 128) w0s[i] = W0[i];
    cvec[tid] = g_cstyle[b * HID + tid];
    cvec[tid + 128] = g_cstyle[b * HID + tid + 128];
    for (int i = tid; i < 192; i += 128) {
        int c = i / 64, px = i - c * 64;
        rgbs[c * 64 + px] = rgb[(size_t)(b * 3 + c) * HW + hw0 + px];
    }
    __syncthreads();

    // ---- layer 0 prologue ----
    {
        int pq = wid & 1, half = wid >> 1;   // 2 px groups x 2 j-halves
        int p = pq * 32 + lane;              // 0..63
        float rr = rgbs[p], gg = rgbs[64 + p], uu = rgbs[128 + p];
        char* arow_p = sm + OFF_A + p * AROWB;
#pragma unroll 4
        for (int q = 0; q < 32; q++) {
            int j = half * 128 + 4 * q;
            float4 wa = *(const float4*)&w0s[j];
            float4 wb = *(const float4*)&w0s[256 + j];
            float4 wc = *(const float4*)&w0s[512 + j];
            float4 cv = *(const float4*)&cvec[j];
            float a0 = fmaf(rr, wa.x, fmaf(gg, wb.x, fmaf(uu, wc.x, cv.x)));
            float a1 = fmaf(rr, wa.y, fmaf(gg, wb.y, fmaf(uu, wc.y, cv.y)));
            float a2 = fmaf(rr, wa.z, fmaf(gg, wb.z, fmaf(uu, wc.z, cv.z)));
            float a3 = fmaf(rr, wa.w, fmaf(gg, wb.w, fmaf(uu, wc.w, cv.w)));
            uint2 st;
            st.x = gelu_h2(pack_h2(a0, a1));
            st.y = gelu_h2(pack_h2(a2, a3));
            *(uint2*)(arow_p + j * 2) = st;
        }
    }
    __syncthreads();

    uint32_t C[4][8][2];
#pragma unroll
    for (int mt = 0; mt < 4; mt++)
#pragma unroll
        for (int nt = 0; nt < 8; nt++) { C[mt][nt][0] = 0u; C[mt][nt][1] = 0u; }

    const uint32_t abase = sb + OFF_A + (uint32_t)arow * AROWB + ak16off;

    // ---- layer 1 (tail prefetches layer-2 ks=0) ----
    run_layer(abase, bp1, bp2, C, bb);
    __syncthreads();
    epi_gelu(sm, C, OFF_B1, ng, lane);
    __syncthreads();

    // ---- layer 2 ----
    run_layer(abase, bp2, nullptr, C, bb);
    __syncthreads();
    epi_gelu(sm, C, OFF_B2, ng, lane);
    __syncthreads();

    // ---- head: A x W3frag (f32 accum), sigmoid, store ----
    {
        const int rbase = wid * 16;          // 4 warps cover 64 rows
        float Ch[4] = {0.f, 0.f, 0.f, 0.f};
        const uint2* wf = g_w3f + lane;
#pragma unroll
        for (int ks = 0; ks < 16; ks++) {
            uint2 bf = __ldg(wf + ks * 32);
            uint32_t ah[4];
            ldsm4(ah, sb + OFF_A + (uint32_t)(rbase + arow) * AROWB
                       + (uint32_t)ks * 32 + ak16off);
            mma16816f(Ch, ah, bf.x, bf.y);
        }
        int c0 = (lane & 3) * 2;
        int r0h = rbase + (lane >> 2);
        if (c0 < 3) {
            float s0 = Ch[0] + b3s[c0];
            float s2 = Ch[2] + b3s[c0];
            out[(size_t)(b * 3 + c0) * HW + hw0 + r0h]     = 1.f / (1.f + expf(-s0));
            out[(size_t)(b * 3 + c0) * HW + hw0 + r0h + 8] = 1.f / (1.f + expf(-s2));
        }
        if (c0 + 1 < 3) {
            float s1 = Ch[1] + b3s[c0 + 1];
            float s3 = Ch[3] + b3s[c0 + 1];
            out[(size_t)(b * 3 + c0 + 1) * HW + hw0 + r0h]     = 1.f / (1.f + expf(-s1));
            out[(size_t)(b * 3 + c0 + 1) * HW + hw0 + r0h + 8] = 1.f / (1.f + expf(-s3));
        }
    }
}

extern "C" void kernel_launch(void* const* d_in, const int* in_sizes, int n_in,
                              void* d_out, int out_size) {
    const float* rgb  = (const float*)d_in[0];
    const int*   sidx = (const int*)  d_in[1];
    const float* emb  = (const float*)d_in[2];
    const float* W0   = (const float*)d_in[3];
    const float* b0   = (const float*)d_in[4];
    const float* W1   = (const float*)d_in[5];
    const float* b1   = (const float*)d_in[6];
    const float* W2   = (const float*)d_in[7];
    const float* b2   = (const float*)d_in[8];
    const float* W3   = (const float*)d_in[9];
    const float* b3   = (const float*)d_in[10];
    float* out = (float*)d_out;

    int B  = in_sizes[1];
    int HW = in_sizes[0] / (3 * B);
    int N  = B * HW;

    prep_all<<<257 + B, 256>>>(W1, W2, sidx, emb, W0, b0, W3, B);

    cudaFuncSetAttribute(nilut_mma, cudaFuncAttributeMaxDynamicSharedMemorySize, SMEM_TOT);
    nilut_mma<<<N / MTILE, 128, SMEM_TOT>>>(rgb, W0, b1, b2, b3, out, HW);
}

// round 17
// speedup vs baseline: 1.5397x; 1.5397x over previous
#include <cuda_runtime.h>
#include <cuda_fp16.h>
#include <cstdint>

#define HID 256
#define MTILE 64

#define AROWB 528
// ---- smem byte offsets (16B aligned) ----
#define OFF_A    0        // 64 * 528 = 33792
#define OFF_B1   33792    // 128 half2
#define OFF_B2   34304    // 128 half2
#define OFF_B3   34816    // 4 f32
#define OFF_W0   34832    // 768 f32
#define OFF_CV   37904    // 256 f32
#define OFF_RGB  38928    // 192 f32
#define SMEM_TOT 39696

// B in PLANE-SPLIT mma-fragment order (coalesced LDG.128):
// uint32 index = (((((l*4 + wn)*16 + ks)*4 + rc)*32 + lane)*4 + q), r = rc*4+q
// value = half2( W[k][n], W[k+1][n] ), n = wn*64 + (r>>1)*8 + lane/4,
//         k = ks*16 + (r&1)*8 + (lane&3)*2
__device__ __align__(16) uint32_t g_bfrag[65536];
// W3 head fragments: [ks16][lane32] x 2 regs (cols 3..7 zero)
__device__ __align__(16) uint2 g_w3f[512];
__device__ float g_cstyle[16 * HID];

// ---------- helpers ----------
__device__ __forceinline__ uint32_t s2u(const void* p) {
    uint32_t a;
    asm("{ .reg .u64 t; cvta.to.shared.u64 t, %1; cvt.u32.u64 %0, t; }" : "=r"(a) : "l"(p));
    return a;
}
__device__ __forceinline__ void ldsm4(uint32_t* r, uint32_t addr) {
    asm volatile("ldmatrix.sync.aligned.m8n8.x4.shared.b16 {%0,%1,%2,%3}, [%4];"
                 : "=r"(r[0]), "=r"(r[1]), "=r"(r[2]), "=r"(r[3]) : "r"(addr));
}
__device__ __forceinline__ uint4 ldcg(const uint4* p) {
    uint4 v;
    asm("ld.global.cg.v4.u32 {%0,%1,%2,%3}, [%4];"
        : "=r"(v.x), "=r"(v.y), "=r"(v.z), "=r"(v.w) : "l"(p));
    return v;
}
__device__ __forceinline__ void mma16816h(uint32_t* d, const uint32_t* a, uint32_t b0, uint32_t b1) {
    asm volatile("mma.sync.aligned.m16n8k16.row.col.f16.f16.f16.f16 "
                 "{%0,%1}, {%2,%3,%4,%5}, {%6,%7}, {%0,%1};"
                 : "+r"(d[0]), "+r"(d[1])
                 : "r"(a[0]), "r"(a[1]), "r"(a[2]), "r"(a[3]), "r"(b0), "r"(b1));
}
__device__ __forceinline__ void mma16816f(float* d, const uint32_t* a, uint32_t b0, uint32_t b1) {
    asm volatile("mma.sync.aligned.m16n8k16.row.col.f32.f16.f16.f32 "
                 "{%0,%1,%2,%3}, {%4,%5,%6,%7}, {%8,%9}, {%0,%1,%2,%3};"
                 : "+f"(d[0]), "+f"(d[1]), "+f"(d[2]), "+f"(d[3])
                 : "r"(a[0]), "r"(a[1]), "r"(a[2]), "r"(a[3]), "r"(b0), "r"(b1));
}
__device__ __forceinline__ uint32_t pack_h2(float lo, float hi) {
    __half2 h = __floats2half2_rn(lo, hi);
    return *(uint32_t*)&h;
}
// tanh-form gelu on a packed half2
__device__ __forceinline__ uint32_t gelu_h2(uint32_t xu) {
    const __half2 C0 = __float2half2_rn(0.7978845608f);
    const __half2 C1 = __float2half2_rn(0.0356774081f);
    const __half2 H5 = __float2half2_rn(0.5f);
    __half2 x = *(__half2*)&xu;
    __half2 x2 = __hmul2(x, x);
    __half2 y = __hmul2(x, __hfma2(x2, C1, C0));
    uint32_t yu = *(uint32_t*)&y, tu;
    asm("tanh.approx.f16x2 %0, %1;" : "=r"(tu) : "r"(yu));
    __half2 t = *(__half2*)&tu;
    __half2 o = __hmul2(x, __hfma2(t, H5, H5));
    return *(uint32_t*)&o;
}

// ---------- merged pre-kernel ----------
__global__ void prep_all(const float* __restrict__ W1, const float* __restrict__ W2,
                         const int* __restrict__ sidx, const float* __restrict__ emb,
                         const float* __restrict__ W0, const float* __restrict__ b0,
                         const float* __restrict__ W3, int B) {
    if (blockIdx.x < 256) {
        int idx = blockIdx.x * 256 + threadIdx.x;    // uint32 index 0..65535
        int q    = idx & 3;
        int lane = (idx >> 2) & 31;
        int rc   = (idx >> 7) & 3;
        int ks   = (idx >> 9) & 15;
        int wn   = (idx >> 13) & 3;
        int l    = (idx >> 15) & 1;
        int r = rc * 4 + q;
        int n = wn * 64 + (r >> 1) * 8 + (lane >> 2);
        int k = ks * 16 + (r & 1) * 8 + (lane & 3) * 2;
        const float* Wm = l ? W2 : W1;
        g_bfrag[idx] = pack_h2(Wm[k * HID + n], Wm[(k + 1) * HID + n]);
    } else if ((int)blockIdx.x < 256 + B) {
        int b = blockIdx.x - 256, j = threadIdx.x;
        int s = sidx[b];
        float acc = b0[j];
#pragma unroll 8
        for (int k = 0; k < 64; k++)
            acc = fmaf(emb[s * 64 + k], W0[(3 + k) * HID + j], acc);
        g_cstyle[b * HID + j] = acc;
    } else {
        for (int e = threadIdx.x; e < 512; e += 256) {
            int ks = e >> 5, lane = e & 31;
            int n = lane >> 2;
            int k0 = ks * 16 + (lane & 3) * 2;
            float v00 = (n < 3) ? W3[k0 * 3 + n] : 0.f;
            float v01 = (n < 3) ? W3[(k0 + 1) * 3 + n] : 0.f;
            float v10 = (n < 3) ? W3[(k0 + 8) * 3 + n] : 0.f;
            float v11 = (n < 3) ? W3[(k0 + 9) * 3 + n] : 0.f;
            g_w3f[e] = make_uint2(pack_h2(v00, v01), pack_h2(v10, v11));
        }
    }
}

// ---------- main kernel ----------
// Software-pipelined layer: A one step ahead, B double-buffered.
// bp points at (layer, wn) base + lane; per ks, 4 coalesced plane loads at +rc*32.
__device__ __forceinline__ void run_layer(uint32_t abase, const uint4* bp, const uint4* bpn,
                                          uint32_t C[4][8][2], uint4 bb[2][4]) {
    uint32_t ahA[4], ahB[4];
    ldsm4(ahA, abase);                 // (ks=0, mt=0)
#pragma unroll
    for (int ks = 0; ks < 16; ks++) {
        uint4* nxt = bb[(ks + 1) & 1];
        const uint4* np = (ks < 15) ? bp + (ks + 1) * 128 : bpn;
        if (np) {
            nxt[0] = ldcg(np);      nxt[1] = ldcg(np + 32);
            nxt[2] = ldcg(np + 64); nxt[3] = ldcg(np + 96);
        }
        const uint32_t* bw = (const uint32_t*)bb[ks & 1];
#pragma unroll
        for (int mt = 0; mt < 4; mt++) {
            const int nmt = (mt + 1) & 3;
            const int nks = (mt == 3) ? ks + 1 : ks;
            if (nks < 16)
                ldsm4(ahB, abase + (uint32_t)nmt * (16 * AROWB) + (uint32_t)nks * 32);
#pragma unroll
            for (int nt = 0; nt < 8; nt++)
                mma16816h(C[mt][nt], ahA, bw[2 * nt], bw[2 * nt + 1]);
#pragma unroll
            for (int q = 0; q < 4; q++) { uint32_t t = ahA[q]; ahA[q] = ahB[q]; ahB[q] = t; }
        }
    }
}

// epilogue: C(half2) + bias -> gelu -> A ; zero C
__device__ __forceinline__ void epi_gelu(char* sm, uint32_t C[4][8][2],
                                         int offB, int ng, int lane) {
    const uint32_t* bh = (const uint32_t*)(sm + offB) + ng * 32 + (lane & 3);
    const int r0b = lane >> 2;
#pragma unroll
    for (int nt = 0; nt < 8; nt++) {
        uint32_t bju = bh[nt * 4];
        __half2 bj = *(__half2*)&bju;
        int j0 = ng * 64 + nt * 8 + (lane & 3) * 2;
#pragma unroll
        for (int mt = 0; mt < 4; mt++) {
            int r0 = r0b + mt * 16, r1 = r0 + 8;
            __half2 c0 = *(__half2*)&C[mt][nt][0];
            __half2 c1 = *(__half2*)&C[mt][nt][1];
            __half2 s0 = __hadd2(c0, bj);
            __half2 s1 = __hadd2(c1, bj);
            *(uint32_t*)(sm + OFF_A + r0 * AROWB + j0 * 2) = gelu_h2(*(uint32_t*)&s0);
            *(uint32_t*)(sm + OFF_A + r1 * AROWB + j0 * 2) = gelu_h2(*(uint32_t*)&s1);
            C[mt][nt][0] = 0u; C[mt][nt][1] = 0u;
        }
    }
}

__global__ void __launch_bounds__(128, 4) nilut_mma(
    const float* __restrict__ rgb, const float* __restrict__ W0,
    const float* __restrict__ b1, const float* __restrict__ b2,
    const float* __restrict__ b3,
    float* __restrict__ out, int HW)
{
    extern __shared__ __align__(1024) char sm[];
    const uint32_t sb = s2u(sm);
    const int tid = threadIdx.x, wid = tid >> 5, lane = tid & 31;

    const int ng = wid;                 // 4 warps, each m64 x n64
    const int arow = lane & 15, ak16off = ((lane >> 4) & 1) * 16;

    const uint4* bp1 = (const uint4*)g_bfrag + (size_t)ng * 2048 + lane;
    const uint4* bp2 = (const uint4*)g_bfrag + (size_t)(4 + ng) * 2048 + lane;

    uint4 bb[2][4];
    bb[0][0] = ldcg(bp1);      bb[0][1] = ldcg(bp1 + 32);
    bb[0][2] = ldcg(bp1 + 64); bb[0][3] = ldcg(bp1 + 96);

    const int pix0 = blockIdx.x * MTILE;
    const int b = pix0 / HW, hw0 = pix0 - b * HW;

    float* b3s = (float*)(sm + OFF_B3);
    float* w0s  = (float*)(sm + OFF_W0);
    float* cvec = (float*)(sm + OFF_CV);
    float* rgbs = (float*)(sm + OFF_RGB);

    ((uint32_t*)(sm + OFF_B1))[tid] = pack_h2(b1[2 * tid], b1[2 * tid + 1]);
    ((uint32_t*)(sm + OFF_B2))[tid] = pack_h2(b2[2 * tid], b2[2 * tid + 1]);
    if (tid < 4) b3s[tid] = (tid < 3) ? b3[tid] : 0.f;
    for (int i = tid; i < 768; i += 128) w0s[i] = W0[i];
    cvec[tid] = g_cstyle[b * HID + tid];
    cvec[tid + 128] = g_cstyle[b * HID + tid + 128];
    for (int i = tid; i < 192; i += 128) {
        int c = i / 64, px = i - c * 64;
        rgbs[c * 64 + px] = rgb[(size_t)(b * 3 + c) * HW + hw0 + px];
    }
    __syncthreads();

    // ---- layer 0 prologue ----
    {
        int pq = wid & 1, half = wid >> 1;   // 2 px groups x 2 j-halves
        int p = pq * 32 + lane;              // 0..63
        float rr = rgbs[p], gg = rgbs[64 + p], uu = rgbs[128 + p];
        char* arow_p = sm + OFF_A + p * AROWB;
#pragma unroll 4
        for (int q = 0; q < 32; q++) {
            int j = half * 128 + 4 * q;
            float4 wa = *(const float4*)&w0s[j];
            float4 wb = *(const float4*)&w0s[256 + j];
            float4 wc = *(const float4*)&w0s[512 + j];
            float4 cv = *(const float4*)&cvec[j];
            float a0 = fmaf(rr, wa.x, fmaf(gg, wb.x, fmaf(uu, wc.x, cv.x)));
            float a1 = fmaf(rr, wa.y, fmaf(gg, wb.y, fmaf(uu, wc.y, cv.y)));
            float a2 = fmaf(rr, wa.z, fmaf(gg, wb.z, fmaf(uu, wc.z, cv.z)));
            float a3 = fmaf(rr, wa.w, fmaf(gg, wb.w, fmaf(uu, wc.w, cv.w)));
            uint2 st;
            st.x = gelu_h2(pack_h2(a0, a1));
            st.y = gelu_h2(pack_h2(a2, a3));
            *(uint2*)(arow_p + j * 2) = st;
        }
    }
    __syncthreads();

    uint32_t C[4][8][2];
#pragma unroll
    for (int mt = 0; mt < 4; mt++)
#pragma unroll
        for (int nt = 0; nt < 8; nt++) { C[mt][nt][0] = 0u; C[mt][nt][1] = 0u; }

    const uint32_t abase = sb + OFF_A + (uint32_t)arow * AROWB + ak16off;

    // ---- layer 1 (tail prefetches layer-2 ks=0) ----
    run_layer(abase, bp1, bp2, C, bb);
    __syncthreads();
    epi_gelu(sm, C, OFF_B1, ng, lane);
    __syncthreads();

    // ---- layer 2 ----
    run_layer(abase, bp2, nullptr, C, bb);
    __syncthreads();
    epi_gelu(sm, C, OFF_B2, ng, lane);
    __syncthreads();

    // ---- head: A x W3frag (f32 accum), sigmoid, store ----
    {
        const int rbase = wid * 16;          // 4 warps cover 64 rows
        float Ch[4] = {0.f, 0.f, 0.f, 0.f};
        const uint2* wf = g_w3f + lane;
#pragma unroll
        for (int ks = 0; ks < 16; ks++) {
            uint2 bf = __ldg(wf + ks * 32);
            uint32_t ah[4];
            ldsm4(ah, sb + OFF_A + (uint32_t)(rbase + arow) * AROWB
                       + (uint32_t)ks * 32 + ak16off);
            mma16816f(Ch, ah, bf.x, bf.y);
        }
        int c0 = (lane & 3) * 2;
        int r0h = rbase + (lane >> 2);
        if (c0 < 3) {
            float s0 = Ch[0] + b3s[c0];
            float s2 = Ch[2] + b3s[c0];
            out[(size_t)(b * 3 + c0) * HW + hw0 + r0h]     = 1.f / (1.f + expf(-s0));
            out[(size_t)(b * 3 + c0) * HW + hw0 + r0h + 8] = 1.f / (1.f + expf(-s2));
        }
        if (c0 + 1 < 3) {
            float s1 = Ch[1] + b3s[c0 + 1];
            float s3 = Ch[3] + b3s[c0 + 1];
            out[(size_t)(b * 3 + c0 + 1) * HW + hw0 + r0h]     = 1.f / (1.f + expf(-s1));
            out[(size_t)(b * 3 + c0 + 1) * HW + hw0 + r0h + 8] = 1.f / (1.f + expf(-s3));
        }
    }
}

extern "C" void kernel_launch(void* const* d_in, const int* in_sizes, int n_in,
                              void* d_out, int out_size) {
    const float* rgb  = (const float*)d_in[0];
    const int*   sidx = (const int*)  d_in[1];
    const float* emb  = (const float*)d_in[2];
    const float* W0   = (const float*)d_in[3];
    const float* b0   = (const float*)d_in[4];
    const float* W1   = (const float*)d_in[5];
    const float* b1   = (const float*)d_in[6];
    const float* W2   = (const float*)d_in[7];
    const float* b2   = (const float*)d_in[8];
    const float* W3   = (const float*)d_in[9];
    const float* b3   = (const float*)d_in[10];
    float* out = (float*)d_out;

    int B  = in_sizes[1];
    int HW = in_sizes[0] / (3 * B);
    int N  = B * HW;

    prep_all<<<257 + B, 256>>>(W1, W2, sidx, emb, W0, b0, W3, B);

    cudaFuncSetAttribute(nilut_mma, cudaFuncAttributeMaxDynamicSharedMemorySize, SMEM_TOT);
    nilut_mma<<<N / MTILE, 128, SMEM_TOT>>>(rgb, W0, b1, b2, b3, out, HW);
}